// round 3
// baseline (speedup 1.0000x reference)
#include <cuda_runtime.h>
#include <cuda_bf16.h>

// HadamardProj: the reference "fwht" pairs adjacent elements (2j, 2j+1) at EVERY
// step, so elements only interact within their pair; 10 steps of H2 on the same
// pair = 32*I, and the d^-0.5 = 1/32 rescale makes each fwht an identity up to
// fp32 rounding. We reproduce the exact rounding sequence per pair:
//   (a,b) *= s0; repeat 4x { 10x [a,b <- a+b, a-b]; *= (s_i * 1/32) }
// using packed f32x2 math (lane0 = pair from d0/d1, lane1 = pair from d2/d3).
// a-b is computed as fma(b, -1, a), which rounds identically to sub.rn.
// Folding 1/32 (a power of two, exact) into s_i is bitwise identical to the
// reference's (x * 1/32) * s_i ordering.

#define NS 5
#define DDIM 1024

typedef unsigned long long u64_t;

__device__ __forceinline__ u64_t pk(float lo, float hi) {
    u64_t r; asm("mov.b64 %0, {%1, %2};" : "=l"(r) : "f"(lo), "f"(hi)); return r;
}
__device__ __forceinline__ void upk(u64_t v, float& lo, float& hi) {
    asm("mov.b64 {%0, %1}, %2;" : "=f"(lo), "=f"(hi) : "l"(v));
}
__device__ __forceinline__ u64_t add2(u64_t a, u64_t b) {
    u64_t r; asm("add.rn.f32x2 %0, %1, %2;" : "=l"(r) : "l"(a), "l"(b)); return r;
}
__device__ __forceinline__ u64_t mul2(u64_t a, u64_t b) {
    u64_t r; asm("mul.rn.f32x2 %0, %1, %2;" : "=l"(r) : "l"(a), "l"(b)); return r;
}
__device__ __forceinline__ u64_t fma2(u64_t a, u64_t b, u64_t c) {
    u64_t r; asm("fma.rn.f32x2 %0, %1, %2, %3;" : "=l"(r) : "l"(a), "l"(b), "l"(c)); return r;
}

__global__ void __launch_bounds__(256)
hadamard_proj_kernel(const float4* __restrict__ x,
                     const float*  __restrict__ scales,
                     float4*       __restrict__ out,
                     int rows) {
    const int t  = threadIdx.x;          // 256 threads cover D=1024 as float4
    const int d0 = t * 4;

    // Per-thread packed scales, loaded once per block lifetime.
    // sa[i] multiplies the "a" lanes (d0, d2); sb[i] the "b" lanes (d1, d3).
    // For i>=1, fold in the exact 1/32 fwht normalization.
    u64_t sa[NS], sb[NS];
#pragma unroll
    for (int i = 0; i < NS; i++) {
        float4 s = *reinterpret_cast<const float4*>(scales + i * DDIM + d0);
        const float f = (i == 0) ? 1.0f : 0.03125f;
        sa[i] = pk(s.x * f, s.z * f);
        sb[i] = pk(s.y * f, s.w * f);
    }

    const u64_t NEG1 = 0xBF800000BF800000ULL;  // packed (-1.0f, -1.0f)

    for (int r = blockIdx.x; r < rows; r += gridDim.x) {
        const size_t base = (size_t)r * (DDIM / 4) + t;
        float4 xv = __ldg(&x[base]);

        u64_t a = mul2(pk(xv.x, xv.z), sa[0]);
        u64_t b = mul2(pk(xv.y, xv.w), sb[0]);

#pragma unroll
        for (int i = 1; i < NS; i++) {
#pragma unroll
            for (int s = 0; s < 10; s++) {
                u64_t tt = add2(a, b);            // a + b
                u64_t uu = fma2(b, NEG1, a);      // a - b (exact neg, rn round)
                a = tt;
                b = uu;
            }
            a = mul2(a, sa[i]);   // (x * 1/32) * s_i  ==  x * (s_i/32) bitwise
            b = mul2(b, sb[i]);
        }

        float4 o;
        upk(a, o.x, o.z);
        upk(b, o.y, o.w);
        out[base] = o;
    }
}

extern "C" void kernel_launch(void* const* d_in, const int* in_sizes, int n_in,
                              void* d_out, int out_size) {
    const float4* x      = (const float4*)d_in[0];
    const float*  scales = (const float*)d_in[1];
    float4*       out    = (float4*)d_out;

    const int rows = in_sizes[0] / DDIM;   // 4 * 4096 = 16384

    // Grid-stride over rows: all blocks resident, scales loaded once per block.
    int grid = 148 * 4;                    // ~28 rows per block
    if (grid > rows) grid = rows;

    hadamard_proj_kernel<<<grid, 256>>>(x, scales, out, rows);
}

// round 5
// speedup vs baseline: 1.0656x; 1.0656x over previous
#include <cuda_runtime.h>
#include <cuda_bf16.h>

// HadamardProj — faithful pair-local replication of the reference "fwht".
// The reference butterfly pairs the SAME adjacent elements (2j,2j+1) every
// step, so the op decomposes into independent 2-element chains:
//   (a,b) *= s0; repeat 4x { 10x [a,b <- a+b, a-b]; *= (s_i/32) }
// Computed with packed f32x2 ops; a-b via fma(b,-1,a) rounds identically to
// sub.rn; 1/32 folded into s_i is exact (power of two). Round-2 measured
// rel_err == 0.0 (bit-exact vs reference).
//
// Round-3 perf changes: prefetch next row-pair ahead of compute (hide DRAM
// latency), 2 independent row chains per thread (ILP=4 on fma pipe),
// streaming ld/st hints, 4 resident blocks/SM.

#define NS 5
#define DDIM 1024
#define TPB 256   // one float4 per thread covers D=1024

typedef unsigned long long u64_t;

__device__ __forceinline__ u64_t pk(float lo, float hi) {
    u64_t r; asm("mov.b64 %0, {%1, %2};" : "=l"(r) : "f"(lo), "f"(hi)); return r;
}
__device__ __forceinline__ void upk(u64_t v, float& lo, float& hi) {
    asm("mov.b64 {%0, %1}, %2;" : "=f"(lo), "=f"(hi) : "l"(v));
}
__device__ __forceinline__ u64_t add2(u64_t a, u64_t b) {
    u64_t r; asm("add.rn.f32x2 %0, %1, %2;" : "=l"(r) : "l"(a), "l"(b)); return r;
}
__device__ __forceinline__ u64_t mul2(u64_t a, u64_t b) {
    u64_t r; asm("mul.rn.f32x2 %0, %1, %2;" : "=l"(r) : "l"(a), "l"(b)); return r;
}
__device__ __forceinline__ u64_t fma2(u64_t a, u64_t b, u64_t c) {
    u64_t r; asm("fma.rn.f32x2 %0, %1, %2, %3;" : "=l"(r) : "l"(a), "l"(b), "l"(c)); return r;
}

__global__ void __launch_bounds__(TPB, 4)
hadamard_proj_kernel(const float4* __restrict__ x,
                     const float*  __restrict__ scales,
                     float4*       __restrict__ out,
                     int rows) {
    const int t = threadIdx.x;
    const int G = gridDim.x;
    const int stride = 2 * G;

    // Packed per-thread scales (loaded once per block lifetime).
    u64_t sa[NS], sb[NS];
#pragma unroll
    for (int i = 0; i < NS; i++) {
        float4 s = __ldg(reinterpret_cast<const float4*>(scales + i * DDIM + t * 4));
        const float f = (i == 0) ? 1.0f : 0.03125f;
        sa[i] = pk(s.x * f, s.z * f);
        sb[i] = pk(s.y * f, s.w * f);
    }

    const u64_t NEG1 = 0xBF800000BF800000ULL;  // packed (-1.0f, -1.0f)
    const size_t rowq = DDIM / 4;              // float4s per row (=256)

    int r = blockIdx.x;
    if (r >= rows) return;

    // Prime the pipeline: load first row pair.
    bool v1 = (r + G) < rows;
    float4 c0 = __ldcs(&x[(size_t)r * rowq + t]);
    float4 c1 = v1 ? __ldcs(&x[(size_t)(r + G) * rowq + t]) : c0;

    for (; r < rows; r += stride) {
        const size_t b0 = (size_t)r * rowq + t;
        const size_t b1 = (size_t)(r + G) * rowq + t;
        const bool cur_v1 = v1;

        // Prefetch next pair before touching compute.
        const int rn = r + stride;
        float4 n0 = c0, n1 = c1;
        bool nv1 = false;
        if (rn < rows) {
            n0  = __ldcs(&x[(size_t)rn * rowq + t]);
            nv1 = (rn + G) < rows;
            if (nv1) n1 = __ldcs(&x[(size_t)(rn + G) * rowq + t]);
        }

        // Two independent butterfly chains, interleaved (ILP = 4).
        u64_t a0 = mul2(pk(c0.x, c0.z), sa[0]);
        u64_t b0p = mul2(pk(c0.y, c0.w), sb[0]);
        u64_t a1 = mul2(pk(c1.x, c1.z), sa[0]);
        u64_t b1p = mul2(pk(c1.y, c1.w), sb[0]);

#pragma unroll
        for (int i = 1; i < NS; i++) {
#pragma unroll
            for (int s = 0; s < 10; s++) {
                u64_t t0 = add2(a0, b0p);
                u64_t t1 = add2(a1, b1p);
                u64_t u0 = fma2(b0p, NEG1, a0);   // a - b, rounds as sub.rn
                u64_t u1 = fma2(b1p, NEG1, a1);
                a0 = t0; b0p = u0;
                a1 = t1; b1p = u1;
            }
            a0 = mul2(a0, sa[i]);  b0p = mul2(b0p, sb[i]);
            a1 = mul2(a1, sa[i]);  b1p = mul2(b1p, sb[i]);
        }

        float4 o0, o1;
        upk(a0, o0.x, o0.z);  upk(b0p, o0.y, o0.w);
        upk(a1, o1.x, o1.z);  upk(b1p, o1.y, o1.w);
        __stcs(&out[b0], o0);
        if (cur_v1) __stcs(&out[b1], o1);

        c0 = n0; c1 = n1; v1 = nv1;
    }
}

extern "C" void kernel_launch(void* const* d_in, const int* in_sizes, int n_in,
                              void* d_out, int out_size) {
    const float4* x      = (const float4*)d_in[0];
    const float*  scales = (const float*)d_in[1];
    float4*       out    = (float4*)d_out;

    const int rows = in_sizes[0] / DDIM;   // 4 * 4096 = 16384

    int grid = 148 * 4;                    // 4 blocks/SM, even wave
    if (grid > rows) grid = rows;

    hadamard_proj_kernel<<<grid, TPB>>>(x, scales, out, rows);
}

// round 7
// speedup vs baseline: 1.1728x; 1.1006x over previous
#include <cuda_runtime.h>
#include <cuda_bf16.h>

// HadamardProj — faithful pair-local replication of the reference "fwht".
// The reference butterfly pairs the SAME adjacent elements (2j,2j+1) every
// step, so the op decomposes into independent 2-element chains:
//   (a,b) *= s0; repeat 4x { 10x [a,b <- a+b, a-b]; *= (s_i/32) }
// Packed f32x2 math; sub.rn.f32x2 rounds identically to the reference's
// subtract; 1/32 folded into s_i is exact (power of two). Measured bit-exact
// (rel_err == 0.0) in rounds 2-4.
//
// Round-5: pair-contiguous grid-stride (rows r, r+1 per iteration; rows is
// even so the hot loop has ZERO validity predicates), pointer-increment
// addressing, 2-deep unconditional prefetch, sub2 instead of fma2+NEG1.

#define NS 5
#define DDIM 1024
#define TPB 256            // one float4 per thread covers D=1024
#define ROWQ (DDIM / 4)    // float4s per row

typedef unsigned long long u64_t;

__device__ __forceinline__ u64_t pk(float lo, float hi) {
    u64_t r; asm("mov.b64 %0, {%1, %2};" : "=l"(r) : "f"(lo), "f"(hi)); return r;
}
__device__ __forceinline__ void upk(u64_t v, float& lo, float& hi) {
    asm("mov.b64 {%0, %1}, %2;" : "=f"(lo), "=f"(hi) : "l"(v));
}
__device__ __forceinline__ u64_t add2(u64_t a, u64_t b) {
    u64_t r; asm("add.rn.f32x2 %0, %1, %2;" : "=l"(r) : "l"(a), "l"(b)); return r;
}
__device__ __forceinline__ u64_t sub2(u64_t a, u64_t b) {
    u64_t r; asm("sub.rn.f32x2 %0, %1, %2;" : "=l"(r) : "l"(a), "l"(b)); return r;
}
__device__ __forceinline__ u64_t mul2(u64_t a, u64_t b) {
    u64_t r; asm("mul.rn.f32x2 %0, %1, %2;" : "=l"(r) : "l"(a), "l"(b)); return r;
}

__global__ void __launch_bounds__(TPB, 4)
hadamard_proj_kernel(const float4* __restrict__ x,
                     const float*  __restrict__ scales,
                     float4*       __restrict__ out,
                     int rows) {
    const int t = threadIdx.x;

    // Packed per-thread scales, loaded once per block lifetime.
    u64_t sa[NS], sb[NS];
#pragma unroll
    for (int i = 0; i < NS; i++) {
        float4 s = __ldg(reinterpret_cast<const float4*>(scales + i * DDIM + t * 4));
        const float f = (i == 0) ? 1.0f : 0.03125f;
        sa[i] = pk(s.x * f, s.z * f);
        sb[i] = pk(s.y * f, s.w * f);
    }

    // Pair-contiguous grid-stride: this block owns row pairs
    // (2*bid, 2*bid+1), (2*bid + 2*G, ...), ...  rows is even (16384), so
    // both rows of a pair are always valid -> no predicates in the hot loop.
    const int  G      = gridDim.x;
    const long step   = (long)2 * G * ROWQ;       // float4 stride per iter
    const int  npairs = rows >> 1;                // 8192
    int        p      = blockIdx.x;               // pair index
    if (p >= npairs) return;
    const int  iters  = (npairs - 1 - p) / G + 1; // pairs this block handles

    const float4* __restrict__ px = x   + (size_t)(2 * p) * ROWQ + t;
    float4*       __restrict__ po = out + (size_t)(2 * p) * ROWQ + t;

    // Prime: load first pair.
    float4 c0 = __ldcs(px);
    float4 c1 = __ldcs(px + ROWQ);

    for (int it = 0; it < iters; it++) {
        // Unconditional prefetch of next pair (guarded only by trip count).
        float4 n0 = c0, n1 = c1;
        if (it + 1 < iters) {
            n0 = __ldcs(px + step);
            n1 = __ldcs(px + step + ROWQ);
        }

        // Two rows' butterfly chains interleaved (ILP = 4 on the fma pipe).
        u64_t a0 = mul2(pk(c0.x, c0.z), sa[0]);
        u64_t b0 = mul2(pk(c0.y, c0.w), sb[0]);
        u64_t a1 = mul2(pk(c1.x, c1.z), sa[0]);
        u64_t b1 = mul2(pk(c1.y, c1.w), sb[0]);

#pragma unroll
        for (int i = 1; i < NS; i++) {
#pragma unroll
            for (int s = 0; s < 10; s++) {
                u64_t t0 = add2(a0, b0);
                u64_t t1 = add2(a1, b1);
                u64_t u0 = sub2(a0, b0);
                u64_t u1 = sub2(a1, b1);
                a0 = t0; b0 = u0;
                a1 = t1; b1 = u1;
            }
            a0 = mul2(a0, sa[i]);  b0 = mul2(b0, sb[i]);
            a1 = mul2(a1, sa[i]);  b1 = mul2(b1, sb[i]);
        }

        float4 o0, o1;
        upk(a0, o0.x, o0.z);  upk(b0, o0.y, o0.w);
        upk(a1, o1.x, o1.z);  upk(b1, o1.y, o1.w);
        __stcs(po, o0);
        __stcs(po + ROWQ, o1);

        px += step; po += step;
        c0 = n0; c1 = n1;
    }
}

extern "C" void kernel_launch(void* const* d_in, const int* in_sizes, int n_in,
                              void* d_out, int out_size) {
    const float4* x      = (const float4*)d_in[0];
    const float*  scales = (const float*)d_in[1];
    float4*       out    = (float4*)d_out;

    const int rows = in_sizes[0] / DDIM;   // 4 * 4096 = 16384

    int grid = 148 * 4;                    // 4 blocks/SM
    const int npairs = rows >> 1;
    if (grid > npairs) grid = npairs;

    hadamard_proj_kernel<<<grid, TPB>>>(x, scales, out, rows);
}